// round 9
// baseline (speedup 1.0000x reference)
#include <cuda_runtime.h>
#include <cuda_bf16.h>
#include <cstdint>
#include <math.h>

// ---------------------------------------------------------------------------
// SchnetConv — edge GEMMs on mma.sync m16n8k16 bf16 (hi/lo 3-term split),
// 32 rows/warp (B fragments amortized 2x), shfl-combined red.global.v4
// epilogue, scalar node MLPs.
// ---------------------------------------------------------------------------

#define Dc       64
#define Rc       128
#define TILE_E   256
#define TILE_N   64
#define WST      68
#define N_MAX    100000

__device__ float g_s[(size_t)N_MAX * Dc];
__device__ float g_cnt[N_MAX];
// fragment-ordered weight image: B1 [8ks][8nt][32lane] uint4{hix,hiy,lox,loy} = 32KB,
// then B2 [4ks][8nt][32lane] uint4 = 16KB
__device__ __align__(16) unsigned char g_Bimg[49152];

// SMEM layout (bytes)
#define OFF_B1    0
#define OFF_B2    32768
#define OFF_A2    49152     // 8 warps x 8KB (hi 4KB | lo 4KB), 32 rows x 128B swizzled
#define OFF_BIAS  114688    // b1[64], b2[64]
#define SMEM_EDGE 115200

// ---- helpers ---------------------------------------------------------------
__device__ __forceinline__ float ssp_f(float x) {
    float e = __expf(-fabsf(x));
    return fmaxf(x, 0.0f) + log1pf(e) - 0.69314718055994531f;
}
__device__ __forceinline__ uint32_t swz(uint32_t off) { return off ^ ((off >> 3) & 0x70); }
__device__ __forceinline__ int wswz(int j) { return j + (((j >> 5) & 1) << 2); }

__device__ __forceinline__ uint32_t smem_u32(const void* p) {
    uint32_t a;
    asm("{ .reg .u64 t; cvta.to.shared.u64 t, %1; cvt.u32.u64 %0, t; }" : "=r"(a) : "l"(p));
    return a;
}
// x = hi + lo (bf16 each); packs (x0 -> low half, x1 -> high half)
__device__ __forceinline__ void split2(float x0, float x1, uint32_t& hi, uint32_t& lo) {
    asm("cvt.rn.bf16x2.f32 %0, %1, %2;" : "=r"(hi) : "f"(x1), "f"(x0));
    float h0 = __uint_as_float(hi << 16);
    float h1 = __uint_as_float(hi & 0xffff0000u);
    asm("cvt.rn.bf16x2.f32 %0, %1, %2;" : "=r"(lo) : "f"(x1 - h1), "f"(x0 - h0));
}
__device__ __forceinline__ void mma16816(float* c, const uint32_t* a, uint32_t b0, uint32_t b1) {
    asm volatile(
        "mma.sync.aligned.m16n8k16.row.col.f32.bf16.bf16.f32 "
        "{%0,%1,%2,%3}, {%4,%5,%6,%7}, {%8,%9}, {%0,%1,%2,%3};"
        : "+f"(c[0]), "+f"(c[1]), "+f"(c[2]), "+f"(c[3])
        : "r"(a[0]), "r"(a[1]), "r"(a[2]), "r"(a[3]), "r"(b0), "r"(b1));
}
__device__ __forceinline__ void ldmx4(uint32_t* r, uint32_t addr) {
    asm volatile("ldmatrix.sync.aligned.m8n8.x4.shared.b16 {%0,%1,%2,%3}, [%4];"
        : "=r"(r[0]), "=r"(r[1]), "=r"(r[2]), "=r"(r[3]) : "r"(addr));
}

// ---------------------------------------------------------------------------
__global__ void zero_kernel(int n_nodes) {
    int i = blockIdx.x * 256 + threadIdx.x;
    int t4 = n_nodes * (Dc / 4);
    if (i < t4) ((float4*)g_s)[i] = make_float4(0.f, 0.f, 0.f, 0.f);
    if (i < n_nodes) g_cnt[i] = 0.0f;
}

// Build fragment-ordered hi/lo weight image. 2048 B1 entries, 1024 B2 entries.
__global__ void prep_kernel(const float* __restrict__ W1, const float* __restrict__ W2) {
    int i = blockIdx.x * 256 + threadIdx.x;
    if (i < 2048) {   // B1: idx = (ks*8+nt)*32+lane
        int lane = i & 31, nt = (i >> 5) & 7, ks = i >> 8;
        int tid4 = lane & 3, g = lane >> 2;
        int k0 = ks * 16 + tid4 * 2;
        int n  = nt * 8 + g;
        float e00 = W1[(k0    ) * Dc + n], e01 = W1[(k0 + 1) * Dc + n];
        float e10 = W1[(k0 + 8) * Dc + n], e11 = W1[(k0 + 9) * Dc + n];
        uint32_t hx, lx, hy, ly;
        split2(e00, e01, hx, lx);
        split2(e10, e11, hy, ly);
        uint4 v; v.x = hx; v.y = hy; v.z = lx; v.w = ly;
        ((uint4*)g_Bimg)[i] = v;
    }
    if (i < 1024) {   // B2
        int lane = i & 31, nt = (i >> 5) & 7, ks = i >> 8;
        int tid4 = lane & 3, g = lane >> 2;
        int k0 = ks * 16 + tid4 * 2;
        int n  = nt * 8 + g;
        float e00 = W2[(k0    ) * Dc + n], e01 = W2[(k0 + 1) * Dc + n];
        float e10 = W2[(k0 + 8) * Dc + n], e11 = W2[(k0 + 9) * Dc + n];
        uint32_t hx, lx, hy, ly;
        split2(e00, e01, hx, lx);
        split2(e10, e11, hy, ly);
        uint4 v; v.x = hx; v.y = hy; v.z = lx; v.w = ly;
        ((uint4*)(g_Bimg + OFF_B2))[i] = v;
    }
}

// ---------------------------------------------------------------------------
// Edge kernel: 256 edges/block, 8 warps x 32 rows (two 16-row MMA halves
// sharing every B fragment load), warp-local pipeline.
// ---------------------------------------------------------------------------
__global__ __launch_bounds__(256, 2)
void edge_kernel(const float* __restrict__ bf, const float* __restrict__ eh,
                 const float* __restrict__ nh, const int* __restrict__ src,
                 const int* __restrict__ dst,
                 const float* __restrict__ b1, const float* __restrict__ b2,
                 int E)
{
    extern __shared__ unsigned char smx[];
    const uint32_t sb = smem_u32(smx);
    const int t = threadIdx.x, w = t >> 5, lane = t & 31;
    const int g = lane >> 2, tid4 = lane & 3;
    const int e0 = blockIdx.x * TILE_E + w * 32;   // warp's first edge row

    // cooperative copy: weight fragments (48KB) + biases
    {
        const uint4* gi = (const uint4*)g_Bimg;
        uint4* s = (uint4*)smx;
        for (int i = t; i < 3072; i += 256) s[i] = gi[i];
        float* sbias = (float*)(smx + OFF_BIAS);
        if (t < Dc) sbias[t] = b1[t];
        else if (t < 2 * Dc) sbias[t] = b2[t - Dc];
    }
    __syncthreads();

    const float* sb1 = (const float*)(smx + OFF_BIAS);
    const float* sb2 = sb1 + Dc;

    // four A rows per lane: (half h, sub s) -> e0 + h*16 + g + s*8
    const float* pr[4];
    bool vr[4];
#pragma unroll
    for (int q = 0; q < 4; ++q) {
        int row = e0 + (q >> 1) * 16 + g + (q & 1) * 8;
        vr[q] = row < E;
        pr[q] = bf + (size_t)min(row, E - 1) * Rc;
    }

    float acc[2][8][4];
#pragma unroll
    for (int h = 0; h < 2; ++h)
#pragma unroll
        for (int nt = 0; nt < 8; ++nt)
#pragma unroll
            for (int q = 0; q < 4; ++q) acc[h][nt][q] = 0.f;

    // ---- GEMM1: f1raw = bf @ W1, K=128 (8 k-steps), N=64 (8 n-tiles) ----
#pragma unroll
    for (int ks = 0; ks < 8; ++ks) {
        const int k0 = ks * 16 + tid4 * 2;
        uint32_t aH[2][4], aL[2][4];
#pragma unroll
        for (int h = 0; h < 2; ++h) {
            float2 x00 = *(const float2*)(pr[h * 2 + 0] + k0);
            float2 x10 = *(const float2*)(pr[h * 2 + 1] + k0);
            float2 x01 = *(const float2*)(pr[h * 2 + 0] + k0 + 8);
            float2 x11 = *(const float2*)(pr[h * 2 + 1] + k0 + 8);
            split2(x00.x, x00.y, aH[h][0], aL[h][0]);
            split2(x10.x, x10.y, aH[h][1], aL[h][1]);
            split2(x01.x, x01.y, aH[h][2], aL[h][2]);
            split2(x11.x, x11.y, aH[h][3], aL[h][3]);
        }
        const uint4* Bp = (const uint4*)(smx + OFF_B1) + (ks * 8) * 32 + lane;
#pragma unroll
        for (int nt = 0; nt < 8; ++nt) {
            uint4 bb = Bp[nt * 32];
            mma16816(acc[0][nt], aH[0], bb.x, bb.y);
            mma16816(acc[0][nt], aH[0], bb.z, bb.w);
            mma16816(acc[0][nt], aL[0], bb.x, bb.y);
            mma16816(acc[1][nt], aH[1], bb.x, bb.y);
            mma16816(acc[1][nt], aH[1], bb.z, bb.w);
            mma16816(acc[1][nt], aL[1], bb.x, bb.y);
        }
    }

    // ---- bias + ssp + hi/lo split -> per-warp A2 strips (swizzled) ----
    const uint32_t aHbase = sb + OFF_A2 + w * 8192;
    const uint32_t aLbase = aHbase + 4096;
#pragma unroll
    for (int h = 0; h < 2; ++h)
#pragma unroll
        for (int nt = 0; nt < 8; ++nt) {
            int n = nt * 8 + tid4 * 2;
            float f0 = ssp_f(acc[h][nt][0] + sb1[n]);
            float f1 = ssp_f(acc[h][nt][1] + sb1[n + 1]);
            float f2 = ssp_f(acc[h][nt][2] + sb1[n]);
            float f3 = ssp_f(acc[h][nt][3] + sb1[n + 1]);
            uint32_t h01, l01, h23, l23;
            split2(f0, f1, h01, l01);
            split2(f2, f3, h23, l23);
            uint32_t o0 = swz((uint32_t)(h * 16 + g)     * 128 + (uint32_t)n * 2);
            uint32_t o1 = swz((uint32_t)(h * 16 + g + 8) * 128 + (uint32_t)n * 2);
            asm volatile("st.shared.b32 [%0], %1;" :: "r"(aHbase + o0), "r"(h01) : "memory");
            asm volatile("st.shared.b32 [%0], %1;" :: "r"(aHbase + o1), "r"(h23) : "memory");
            asm volatile("st.shared.b32 [%0], %1;" :: "r"(aLbase + o0), "r"(l01) : "memory");
            asm volatile("st.shared.b32 [%0], %1;" :: "r"(aLbase + o1), "r"(l23) : "memory");
#pragma unroll
            for (int q = 0; q < 4; ++q) acc[h][nt][q] = 0.f;
        }
    __syncwarp();

    // ---- GEMM2: f2raw = f1 @ W2, K=64 (4 k-steps) ----
    {
        const int lrow = lane & 15, half16 = lane >> 4;
#pragma unroll
        for (int ks = 0; ks < 4; ++ks) {
            uint32_t aH[2][4], aL[2][4];
#pragma unroll
            for (int h = 0; h < 2; ++h) {
                uint32_t off = swz((uint32_t)(h * 16 + lrow) * 128
                                   + (uint32_t)ks * 32 + (uint32_t)half16 * 16);
                ldmx4(aH[h], aHbase + off);
                ldmx4(aL[h], aLbase + off);
            }
            const uint4* Bp = (const uint4*)(smx + OFF_B2) + (ks * 8) * 32 + lane;
#pragma unroll
            for (int nt = 0; nt < 8; ++nt) {
                uint4 bb = Bp[nt * 32];
                mma16816(acc[0][nt], aH[0], bb.x, bb.y);
                mma16816(acc[0][nt], aH[0], bb.z, bb.w);
                mma16816(acc[0][nt], aL[0], bb.x, bb.y);
                mma16816(acc[1][nt], aH[1], bb.x, bb.y);
                mma16816(acc[1][nt], aH[1], bb.z, bb.w);
                mma16816(acc[1][nt], aL[1], bb.x, bb.y);
            }
        }
    }

    // ---- epilogue: m = f2 * eh * nh[src]; shfl-combine -> red.global.v4 ----
#pragma unroll
    for (int h = 0; h < 2; ++h)
#pragma unroll
        for (int s = 0; s < 2; ++s) {
            const int row = e0 + h * 16 + g + s * 8;
            const bool vv = vr[h * 2 + s];
            int sv = 0, dv = 0;
            if (vv) { sv = src[row]; dv = dst[row]; }
            if (vv && tid4 == 0) atomicAdd(&g_cnt[dv], 1.0f);
#pragma unroll
            for (int nt = 0; nt < 8; ++nt) {
                int n = nt * 8 + tid4 * 2;
                float f0 = ssp_f(acc[h][nt][s * 2 + 0] + sb2[n]);
                float f1 = ssp_f(acc[h][nt][s * 2 + 1] + sb2[n + 1]);
                float f2p = __shfl_down_sync(0xffffffffu, f0, 1);
                float f3p = __shfl_down_sync(0xffffffffu, f1, 1);
                if (vv && !(tid4 & 1)) {
                    int n4 = nt * 8 + tid4 * 2;   // tid4 in {0,2} -> n4 in {nt8, nt8+4}
                    float4 ev = *(const float4*)&eh[(size_t)row * Dc + n4];
                    float4 nv = *(const float4*)&nh[(size_t)sv * Dc + n4];
                    float m0 = f0  * ev.x * nv.x;
                    float m1 = f1  * ev.y * nv.y;
                    float m2 = f2p * ev.z * nv.z;
                    float m3 = f3p * ev.w * nv.w;
                    float* gp = &g_s[(size_t)dv * Dc + n4];
                    asm volatile("red.global.add.v4.f32 [%0], {%1, %2, %3, %4};"
                                 :: "l"(gp), "f"(m0), "f"(m1), "f"(m2), "f"(m3) : "memory");
                }
            }
        }
}

// ---------------------------------------------------------------------------
// Node kernel: mean -> MLP3 -> MLP4 (validated in R5/R8)
// ---------------------------------------------------------------------------
__global__ __launch_bounds__(256)
void node_kernel(const float* __restrict__ W3, const float* __restrict__ b3,
                 const float* __restrict__ W4, const float* __restrict__ b4,
                 float* __restrict__ out, int N)
{
    extern __shared__ float sm[];
    float* W3s  = sm;
    float* W4s  = W3s + Dc * WST;
    float* b3s  = W4s + Dc * WST;
    float* b4s  = b3s + Dc;
    float* cS   = b4s + Dc;
    float* aggS = cS + TILE_N;
    float* h1S  = aggS + TILE_N * WST;

    const int t      = threadIdx.x;
    const int n_base = blockIdx.x * TILE_N;

    for (int i = t; i < Dc * Dc; i += 256) {
        int k = i >> 6, j = i & 63;
        int js = wswz(j);
        W3s[k * WST + js] = W3[i];
        W4s[k * WST + js] = W4[i];
    }
    if (t < Dc) { b3s[t] = b3[t]; b4s[t] = b4[t]; }
    if (t < TILE_N) {
        int n = n_base + t;
        float c = (n < N) ? g_cnt[n] : 0.0f;
        cS[t] = (c > 0.0f) ? (1.0f / c) : 0.0f;
    }
    __syncthreads();

    for (int i4 = t; i4 < TILE_N * (Dc / 4); i4 += 256) {
        int nl = i4 >> 4;
        int k4 = (i4 & 15) << 2;
        int n  = n_base + nl;
        float4 v = make_float4(0.f, 0.f, 0.f, 0.f);
        if (n < N) {
            v = *(const float4*)&g_s[(size_t)n * Dc + k4];
            float inv = cS[nl];
            v.x *= inv; v.y *= inv; v.z *= inv; v.w *= inv;
        }
        *(float4*)&aggS[nl * WST + k4] = v;
    }
    __syncthreads();

    const int tj = t & 7;
    const int tn = t >> 3;
    const int j0 = tj << 3;
    const int jo = wswz(j0);
    const int n0 = tn << 1;

    float acc[2][8];
#pragma unroll
    for (int a = 0; a < 2; ++a)
#pragma unroll
        for (int b = 0; b < 8; ++b) acc[a][b] = 0.f;

#pragma unroll 8
    for (int k = 0; k < Dc; ++k) {
        float4 wA = *(const float4*)&W3s[k * WST + jo];
        float4 wB = *(const float4*)&W3s[k * WST + jo + 4];
        float w[8] = {wA.x, wA.y, wA.z, wA.w, wB.x, wB.y, wB.z, wB.w};
        float x0 = aggS[(n0 + 0) * WST + k];
        float x1 = aggS[(n0 + 1) * WST + k];
#pragma unroll
        for (int b = 0; b < 8; ++b) {
            acc[0][b] = fmaf(x0, w[b], acc[0][b]);
            acc[1][b] = fmaf(x1, w[b], acc[1][b]);
        }
    }
#pragma unroll
    for (int a = 0; a < 2; ++a) {
        float h[8];
#pragma unroll
        for (int b = 0; b < 8; ++b) h[b] = ssp_f(acc[a][b] + b3s[j0 + b]);
        *(float4*)&h1S[(n0 + a) * WST + j0]     = make_float4(h[0], h[1], h[2], h[3]);
        *(float4*)&h1S[(n0 + a) * WST + j0 + 4] = make_float4(h[4], h[5], h[6], h[7]);
#pragma unroll
        for (int b = 0; b < 8; ++b) acc[a][b] = 0.f;
    }
    __syncthreads();

#pragma unroll 8
    for (int k = 0; k < Dc; ++k) {
        float4 wA = *(const float4*)&W4s[k * WST + jo];
        float4 wB = *(const float4*)&W4s[k * WST + jo + 4];
        float w[8] = {wA.x, wA.y, wA.z, wA.w, wB.x, wB.y, wB.z, wB.w};
        float x0 = h1S[(n0 + 0) * WST + k];
        float x1 = h1S[(n0 + 1) * WST + k];
#pragma unroll
        for (int b = 0; b < 8; ++b) {
            acc[0][b] = fmaf(x0, w[b], acc[0][b]);
            acc[1][b] = fmaf(x1, w[b], acc[1][b]);
        }
    }
#pragma unroll
    for (int a = 0; a < 2; ++a) {
        int n = n_base + n0 + a;
        if (n < N) {
            float o[8];
#pragma unroll
            for (int b = 0; b < 8; ++b) o[b] = ssp_f(acc[a][b] + b4s[j0 + b]);
            *(float4*)&out[(size_t)n * Dc + j0]     = make_float4(o[0], o[1], o[2], o[3]);
            *(float4*)&out[(size_t)n * Dc + j0 + 4] = make_float4(o[4], o[5], o[6], o[7]);
        }
    }
}

// ---------------------------------------------------------------------------
extern "C" void kernel_launch(void* const* d_in, const int* in_sizes, int n_in,
                              void* d_out, int out_size)
{
    const float* bf  = (const float*)d_in[0];
    const float* eh  = (const float*)d_in[1];
    const float* nh  = (const float*)d_in[2];
    const int*   src = (const int*)  d_in[3];
    const int*   dst = (const int*)  d_in[4];
    const float* W1  = (const float*)d_in[5];
    const float* b1  = (const float*)d_in[6];
    const float* W2  = (const float*)d_in[7];
    const float* b2  = (const float*)d_in[8];
    const float* W3  = (const float*)d_in[9];
    const float* b3  = (const float*)d_in[10];
    const float* W4  = (const float*)d_in[11];
    const float* b4  = (const float*)d_in[12];

    int E = in_sizes[3];
    int N = in_sizes[2] / Dc;

    const int NODE_SMEM = (2 * Dc * WST + 2 * Dc + TILE_N + 2 * TILE_N * WST) * (int)sizeof(float);

    cudaFuncSetAttribute(edge_kernel, cudaFuncAttributeMaxDynamicSharedMemorySize, SMEM_EDGE);
    cudaFuncSetAttribute(node_kernel, cudaFuncAttributeMaxDynamicSharedMemorySize, NODE_SMEM);

    int zero_grid = (N * (Dc / 4) + 255) / 256;
    zero_kernel<<<zero_grid, 256>>>(N);

    prep_kernel<<<8, 256>>>(W1, W2);

    int edge_grid = (E + TILE_E - 1) / TILE_E;
    edge_kernel<<<edge_grid, 256, SMEM_EDGE>>>(bf, eh, nh, src, dst, b1, b2, E);

    int node_grid = (N + TILE_N - 1) / TILE_N;
    node_kernel<<<node_grid, 256, NODE_SMEM>>>(W3, b3, W4, b4, (float*)d_out, N);
}

// round 10
// speedup vs baseline: 1.0254x; 1.0254x over previous
#include <cuda_runtime.h>
#include <cuda_bf16.h>
#include <cstdint>
#include <math.h>

// ---------------------------------------------------------------------------
// SchnetConv — edge GEMMs on tensor cores via mma.sync m16n8k16 bf16 (hi/lo
// 3-term split), warp-local pipeline (R8 structure), shfl-combined
// red.global.add.v4 epilogue. Scalar node MLPs.
// ---------------------------------------------------------------------------

#define Dc       64
#define Rc       128
#define TILE_E   128
#define TILE_N   64
#define WST      68
#define N_MAX    100000

__device__ float g_s[(size_t)N_MAX * Dc];
__device__ float g_cnt[N_MAX];
// fragment-ordered weight image: B1 [8ks][8nt][32lane] uint4{hix,hiy,lox,loy} =32KB,
// then B2 [4ks][8nt][32lane] uint4 = 16KB
__device__ __align__(16) unsigned char g_Bimg[49152];

// SMEM layout (bytes)
#define OFF_B1    0
#define OFF_B2    32768
#define OFF_A2HI  49152     // 8 warps x 2048B (16 rows x 128B, swizzled)
#define OFF_A2LO  65536
#define OFF_BIAS  81920     // b1[64], b2[64]
#define SMEM_EDGE 82432

// ---- helpers ---------------------------------------------------------------
__device__ __forceinline__ float ssp_f(float x) {
    float e = __expf(-fabsf(x));
    return fmaxf(x, 0.0f) + log1pf(e) - 0.69314718055994531f;
}
__device__ __forceinline__ uint32_t swz(uint32_t off) { return off ^ ((off >> 3) & 0x70); }
__device__ __forceinline__ int wswz(int j) { return j + (((j >> 5) & 1) << 2); }

__device__ __forceinline__ uint32_t smem_u32(const void* p) {
    uint32_t a;
    asm("{ .reg .u64 t; cvta.to.shared.u64 t, %1; cvt.u32.u64 %0, t; }" : "=r"(a) : "l"(p));
    return a;
}
// x = hi + lo (bf16 each); packs (x0 -> low half, x1 -> high half)
__device__ __forceinline__ void split2(float x0, float x1, uint32_t& hi, uint32_t& lo) {
    asm("cvt.rn.bf16x2.f32 %0, %1, %2;" : "=r"(hi) : "f"(x1), "f"(x0));
    float h0 = __uint_as_float(hi << 16);
    float h1 = __uint_as_float(hi & 0xffff0000u);
    asm("cvt.rn.bf16x2.f32 %0, %1, %2;" : "=r"(lo) : "f"(x1 - h1), "f"(x0 - h0));
}
__device__ __forceinline__ void mma16816(float* c, const uint32_t* a, uint32_t b0, uint32_t b1) {
    asm volatile(
        "mma.sync.aligned.m16n8k16.row.col.f32.bf16.bf16.f32 "
        "{%0,%1,%2,%3}, {%4,%5,%6,%7}, {%8,%9}, {%0,%1,%2,%3};"
        : "+f"(c[0]), "+f"(c[1]), "+f"(c[2]), "+f"(c[3])
        : "r"(a[0]), "r"(a[1]), "r"(a[2]), "r"(a[3]), "r"(b0), "r"(b1));
}
__device__ __forceinline__ void ldmx4(uint32_t* r, uint32_t addr) {
    asm volatile("ldmatrix.sync.aligned.m8n8.x4.shared.b16 {%0,%1,%2,%3}, [%4];"
        : "=r"(r[0]), "=r"(r[1]), "=r"(r[2]), "=r"(r[3]) : "r"(addr));
}

// ---------------------------------------------------------------------------
__global__ void zero_kernel(int n_nodes) {
    int i = blockIdx.x * 256 + threadIdx.x;
    int t4 = n_nodes * (Dc / 4);
    if (i < t4) ((float4*)g_s)[i] = make_float4(0.f, 0.f, 0.f, 0.f);
    if (i < n_nodes) g_cnt[i] = 0.0f;
}

// Build fragment-ordered hi/lo weight image. 2048 B1 entries, 1024 B2 entries.
__global__ void prep_kernel(const float* __restrict__ W1, const float* __restrict__ W2) {
    int i = blockIdx.x * 256 + threadIdx.x;
    if (i < 2048) {   // B1: idx = (ks*8+nt)*32+lane
        int lane = i & 31, nt = (i >> 5) & 7, ks = i >> 8;
        int tid4 = lane & 3, g = lane >> 2;
        int k0 = ks * 16 + tid4 * 2;
        int n  = nt * 8 + g;
        float e00 = W1[(k0    ) * Dc + n], e01 = W1[(k0 + 1) * Dc + n];
        float e10 = W1[(k0 + 8) * Dc + n], e11 = W1[(k0 + 9) * Dc + n];
        uint32_t hx, lx, hy, ly;
        split2(e00, e01, hx, lx);
        split2(e10, e11, hy, ly);
        uint4 v; v.x = hx; v.y = hy; v.z = lx; v.w = ly;
        ((uint4*)g_Bimg)[i] = v;
    }
    if (i < 1024) {   // B2
        int lane = i & 31, nt = (i >> 5) & 7, ks = i >> 8;
        int tid4 = lane & 3, g = lane >> 2;
        int k0 = ks * 16 + tid4 * 2;
        int n  = nt * 8 + g;
        float e00 = W2[(k0    ) * Dc + n], e01 = W2[(k0 + 1) * Dc + n];
        float e10 = W2[(k0 + 8) * Dc + n], e11 = W2[(k0 + 9) * Dc + n];
        uint32_t hx, lx, hy, ly;
        split2(e00, e01, hx, lx);
        split2(e10, e11, hy, ly);
        uint4 v; v.x = hx; v.y = hy; v.z = lx; v.w = ly;
        ((uint4*)(g_Bimg + OFF_B2))[i] = v;
    }
}

// ---------------------------------------------------------------------------
// Edge kernel: 128 edges/block, 8 warps x 16 rows, warp-local pipeline.
// ---------------------------------------------------------------------------
__global__ __launch_bounds__(256, 2)
void edge_kernel(const float* __restrict__ bf, const float* __restrict__ eh,
                 const float* __restrict__ nh, const int* __restrict__ src,
                 const int* __restrict__ dst,
                 const float* __restrict__ b1, const float* __restrict__ b2,
                 int E)
{
    extern __shared__ unsigned char smx[];
    const uint32_t sb = smem_u32(smx);
    const int t = threadIdx.x, w = t >> 5, lane = t & 31;
    const int g = lane >> 2, tid4 = lane & 3;
    const int e0 = blockIdx.x * TILE_E + w * 16;   // warp's first edge row

    // cooperative copy: weight fragments (48KB) + biases
    {
        const uint4* gi = (const uint4*)g_Bimg;
        uint4* s = (uint4*)smx;
        for (int i = t; i < 3072; i += 256) s[i] = gi[i];
        float* sbias = (float*)(smx + OFF_BIAS);
        if (t < Dc) sbias[t] = b1[t];
        else if (t < 2 * Dc) sbias[t] = b2[t - Dc];
    }
    __syncthreads();

    const float* sb1 = (const float*)(smx + OFF_BIAS);
    const float* sb2 = sb1 + Dc;

    // clamp row pointers (grid guarantees e0 < E; rows may exceed on ragged tail)
    const int er0 = min(e0 + g,     E - 1);
    const int er1 = min(e0 + g + 8, E - 1);
    const bool v0 = (e0 + g)     < E;
    const bool v1 = (e0 + g + 8) < E;
    const float* p0 = bf + (size_t)er0 * Rc;
    const float* p1 = bf + (size_t)er1 * Rc;

    float acc[8][4];
#pragma unroll
    for (int nt = 0; nt < 8; ++nt)
#pragma unroll
        for (int q = 0; q < 4; ++q) acc[nt][q] = 0.f;

    // ---- GEMM1: f1raw = bf @ W1, K=128 (8 k-steps), N=64 (8 n-tiles) ----
#pragma unroll
    for (int ks = 0; ks < 8; ++ks) {
        const int k0 = ks * 16 + tid4 * 2;
        float2 x00 = *(const float2*)(p0 + k0);
        float2 x10 = *(const float2*)(p1 + k0);
        float2 x01 = *(const float2*)(p0 + k0 + 8);
        float2 x11 = *(const float2*)(p1 + k0 + 8);
        uint32_t aH[4], aL[4];
        split2(x00.x, x00.y, aH[0], aL[0]);
        split2(x10.x, x10.y, aH[1], aL[1]);
        split2(x01.x, x01.y, aH[2], aL[2]);
        split2(x11.x, x11.y, aH[3], aL[3]);
        const uint4* Bp = (const uint4*)(smx + OFF_B1) + (ks * 8) * 32 + lane;
#pragma unroll
        for (int nt = 0; nt < 8; ++nt) {
            uint4 bb = Bp[nt * 32];
            mma16816(acc[nt], aH, bb.x, bb.y);   // Ah*Bh
            mma16816(acc[nt], aH, bb.z, bb.w);   // Ah*Bl
            mma16816(acc[nt], aL, bb.x, bb.y);   // Al*Bh
        }
    }

    // ---- bias + ssp + hi/lo split -> per-warp A2 strips (swizzled) ----
    {
        const uint32_t aHbase = sb + OFF_A2HI + w * 2048;
        const uint32_t aLbase = sb + OFF_A2LO + w * 2048;
#pragma unroll
        for (int nt = 0; nt < 8; ++nt) {
            int n = nt * 8 + tid4 * 2;
            float f0 = ssp_f(acc[nt][0] + sb1[n]);
            float f1 = ssp_f(acc[nt][1] + sb1[n + 1]);
            float f2 = ssp_f(acc[nt][2] + sb1[n]);
            float f3 = ssp_f(acc[nt][3] + sb1[n + 1]);
            uint32_t h01, l01, h23, l23;
            split2(f0, f1, h01, l01);
            split2(f2, f3, h23, l23);
            uint32_t o0 = swz((uint32_t)g       * 128 + (uint32_t)n * 2);
            uint32_t o1 = swz((uint32_t)(g + 8) * 128 + (uint32_t)n * 2);
            asm volatile("st.shared.b32 [%0], %1;" :: "r"(aHbase + o0), "r"(h01) : "memory");
            asm volatile("st.shared.b32 [%0], %1;" :: "r"(aHbase + o1), "r"(h23) : "memory");
            asm volatile("st.shared.b32 [%0], %1;" :: "r"(aLbase + o0), "r"(l01) : "memory");
            asm volatile("st.shared.b32 [%0], %1;" :: "r"(aLbase + o1), "r"(l23) : "memory");
#pragma unroll
            for (int q = 0; q < 4; ++q) acc[nt][q] = 0.f;
        }
    }
    __syncwarp();

    // ---- GEMM2: f2raw = f1 @ W2, K=64 (4 k-steps) ----
    {
        const int lrow = lane & 15, half = lane >> 4;
        const uint32_t aHbase = sb + OFF_A2HI + w * 2048;
        const uint32_t aLbase = sb + OFF_A2LO + w * 2048;
#pragma unroll
        for (int ks = 0; ks < 4; ++ks) {
            uint32_t off = swz((uint32_t)lrow * 128 + (uint32_t)ks * 32 + (uint32_t)half * 16);
            uint32_t aH[4], aL[4];
            ldmx4(aH, aHbase + off);
            ldmx4(aL, aLbase + off);
            const uint4* Bp = (const uint4*)(smx + OFF_B2) + (ks * 8) * 32 + lane;
#pragma unroll
            for (int nt = 0; nt < 8; ++nt) {
                uint4 bb = Bp[nt * 32];
                mma16816(acc[nt], aH, bb.x, bb.y);
                mma16816(acc[nt], aH, bb.z, bb.w);
                mma16816(acc[nt], aL, bb.x, bb.y);
            }
        }
    }

    // ---- epilogue: m = f2 * eh * nh[src]; shfl-combine -> red.global.v4 ----
    int sv0 = 0, dv0 = 0, sv1 = 0, dv1 = 0;
    if (v0) { sv0 = src[e0 + g];     dv0 = dst[e0 + g]; }
    if (v1) { sv1 = src[e0 + g + 8]; dv1 = dst[e0 + g + 8]; }
    if (tid4 == 0) {
        if (v0) atomicAdd(&g_cnt[dv0], 1.0f);
        if (v1) atomicAdd(&g_cnt[dv1], 1.0f);
    }
#pragma unroll
    for (int nt = 0; nt < 8; ++nt) {
        const int n = nt * 8 + tid4 * 2;
        // row 0 (c0/c1), row 1 (c2/c3) — apply bias+ssp on all lanes
        float f0 = ssp_f(acc[nt][0] + sb2[n]);
        float f1 = ssp_f(acc[nt][1] + sb2[n + 1]);
        float f2 = ssp_f(acc[nt][2] + sb2[n]);
        float f3 = ssp_f(acc[nt][3] + sb2[n + 1]);
        // odd tid4 lanes hand their pair to the even neighbor
        float f0p = __shfl_down_sync(0xffffffffu, f0, 1);
        float f1p = __shfl_down_sync(0xffffffffu, f1, 1);
        float f2p = __shfl_down_sync(0xffffffffu, f2, 1);
        float f3p = __shfl_down_sync(0xffffffffu, f3, 1);
        if (!(tid4 & 1)) {
            // even lane owns n4 = nt*8 + tid4*2 (tid4 in {0,2} -> offsets {0,4})
            if (v0) {
                float4 ev = *(const float4*)&eh[(size_t)(e0 + g) * Dc + n];
                float4 nv = *(const float4*)&nh[(size_t)sv0 * Dc + n];
                float m0 = f0  * ev.x * nv.x;
                float m1 = f1  * ev.y * nv.y;
                float m2 = f0p * ev.z * nv.z;
                float m3 = f1p * ev.w * nv.w;
                float* gp = &g_s[(size_t)dv0 * Dc + n];
                asm volatile("red.global.add.v4.f32 [%0], {%1, %2, %3, %4};"
                             :: "l"(gp), "f"(m0), "f"(m1), "f"(m2), "f"(m3) : "memory");
            }
            if (v1) {
                float4 ev = *(const float4*)&eh[(size_t)(e0 + g + 8) * Dc + n];
                float4 nv = *(const float4*)&nh[(size_t)sv1 * Dc + n];
                float m0 = f2  * ev.x * nv.x;
                float m1 = f3  * ev.y * nv.y;
                float m2 = f2p * ev.z * nv.z;
                float m3 = f3p * ev.w * nv.w;
                float* gp = &g_s[(size_t)dv1 * Dc + n];
                asm volatile("red.global.add.v4.f32 [%0], {%1, %2, %3, %4};"
                             :: "l"(gp), "f"(m0), "f"(m1), "f"(m2), "f"(m3) : "memory");
            }
        }
    }
}

// ---------------------------------------------------------------------------
// Node kernel: mean -> MLP3 -> MLP4 (validated in R5/R8)
// ---------------------------------------------------------------------------
__global__ __launch_bounds__(256)
void node_kernel(const float* __restrict__ W3, const float* __restrict__ b3,
                 const float* __restrict__ W4, const float* __restrict__ b4,
                 float* __restrict__ out, int N)
{
    extern __shared__ float sm[];
    float* W3s  = sm;
    float* W4s  = W3s + Dc * WST;
    float* b3s  = W4s + Dc * WST;
    float* b4s  = b3s + Dc;
    float* cS   = b4s + Dc;
    float* aggS = cS + TILE_N;
    float* h1S  = aggS + TILE_N * WST;

    const int t      = threadIdx.x;
    const int n_base = blockIdx.x * TILE_N;

    for (int i = t; i < Dc * Dc; i += 256) {
        int k = i >> 6, j = i & 63;
        int js = wswz(j);
        W3s[k * WST + js] = W3[i];
        W4s[k * WST + js] = W4[i];
    }
    if (t < Dc) { b3s[t] = b3[t]; b4s[t] = b4[t]; }
    if (t < TILE_N) {
        int n = n_base + t;
        float c = (n < N) ? g_cnt[n] : 0.0f;
        cS[t] = (c > 0.0f) ? (1.0f / c) : 0.0f;
    }
    __syncthreads();

    for (int i4 = t; i4 < TILE_N * (Dc / 4); i4 += 256) {
        int nl = i4 >> 4;
        int k4 = (i4 & 15) << 2;
        int n  = n_base + nl;
        float4 v = make_float4(0.f, 0.f, 0.f, 0.f);
        if (n < N) {
            v = *(const float4*)&g_s[(size_t)n * Dc + k4];
            float inv = cS[nl];
            v.x *= inv; v.y *= inv; v.z *= inv; v.w *= inv;
        }
        *(float4*)&aggS[nl * WST + k4] = v;
    }
    __syncthreads();

    const int tj = t & 7;
    const int tn = t >> 3;
    const int j0 = tj << 3;
    const int jo = wswz(j0);
    const int n0 = tn << 1;

    float acc[2][8];
#pragma unroll
    for (int a = 0; a < 2; ++a)
#pragma unroll
        for (int b = 0; b < 8; ++b) acc[a][b] = 0.f;

#pragma unroll 8
    for (int k = 0; k < Dc; ++k) {
        float4 wA = *(const float4*)&W3s[k * WST + jo];
        float4 wB = *(const float4*)&W3s[k * WST + jo + 4];
        float w[8] = {wA.x, wA.y, wA.z, wA.w, wB.x, wB.y, wB.z, wB.w};
        float x0 = aggS[(n0 + 0) * WST + k];
        float x1 = aggS[(n0 + 1) * WST + k];
#pragma unroll
        for (int b = 0; b < 8; ++b) {
            acc[0][b] = fmaf(x0, w[b], acc[0][b]);
            acc[1][b] = fmaf(x1, w[b], acc[1][b]);
        }
    }
#pragma unroll
    for (int a = 0; a < 2; ++a) {
        float h[8];
#pragma unroll
        for (int b = 0; b < 8; ++b) h[b] = ssp_f(acc[a][b] + b3s[j0 + b]);
        *(float4*)&h1S[(n0 + a) * WST + j0]     = make_float4(h[0], h[1], h[2], h[3]);
        *(float4*)&h1S[(n0 + a) * WST + j0 + 4] = make_float4(h[4], h[5], h[6], h[7]);
#pragma unroll
        for (int b = 0; b < 8; ++b) acc[a][b] = 0.f;
    }
    __syncthreads();

#pragma unroll 8
    for (int k = 0; k < Dc; ++k) {
        float4 wA = *(const float4*)&W4s[k * WST + jo];
        float4 wB = *(const float4*)&W4s[k * WST + jo + 4];
        float w[8] = {wA.x, wA.y, wA.z, wA.w, wB.x, wB.y, wB.z, wB.w};
        float x0 = h1S[(n0 + 0) * WST + k];
        float x1 = h1S[(n0 + 1) * WST + k];
#pragma unroll
        for (int b = 0; b < 8; ++b) {
            acc[0][b] = fmaf(x0, w[b], acc[0][b]);
            acc[1][b] = fmaf(x1, w[b], acc[1][b]);
        }
    }
#pragma unroll
    for (int a = 0; a < 2; ++a) {
        int n = n_base + n0 + a;
        if (n < N) {
            float o[8];
#pragma unroll
            for (int b = 0; b < 8; ++b) o[b] = ssp_f(acc[a][b] + b4s[j0 + b]);
            *(float4*)&out[(size_t)n * Dc + j0]     = make_float4(o[0], o[1], o[2], o[3]);
            *(float4*)&out[(size_t)n * Dc + j0 + 4] = make_float4(o[4], o[5], o[6], o[7]);
        }
    }
}

// ---------------------------------------------------------------------------
extern "C" void kernel_launch(void* const* d_in, const int* in_sizes, int n_in,
                              void* d_out, int out_size)
{
    const float* bf  = (const float*)d_in[0];
    const float* eh  = (const float*)d_in[1];
    const float* nh  = (const float*)d_in[2];
    const int*   src = (const int*)  d_in[3];
    const int*   dst = (const int*)  d_in[4];
    const float* W1  = (const float*)d_in[5];
    const float* b1  = (const float*)d_in[6];
    const float* W2  = (const float*)d_in[7];
    const float* b2  = (const float*)d_in[8];
    const float* W3  = (const float*)d_in[9];
    const float* b3  = (const float*)d_in[10];
    const float* W4  = (const float*)d_in[11];
    const float* b4  = (const float*)d_in[12];

    int E = in_sizes[3];
    int N = in_sizes[2] / Dc;

    const int NODE_SMEM = (2 * Dc * WST + 2 * Dc + TILE_N + 2 * TILE_N * WST) * (int)sizeof(float);

    cudaFuncSetAttribute(edge_kernel, cudaFuncAttributeMaxDynamicSharedMemorySize, SMEM_EDGE);
    cudaFuncSetAttribute(node_kernel, cudaFuncAttributeMaxDynamicSharedMemorySize, NODE_SMEM);

    int zero_grid = (N * (Dc / 4) + 255) / 256;
    zero_kernel<<<zero_grid, 256>>>(N);

    prep_kernel<<<8, 256>>>(W1, W2);

    int edge_grid = (E + TILE_E - 1) / TILE_E;
    edge_kernel<<<edge_grid, 256, SMEM_EDGE>>>(bf, eh, nh, src, dst, b1, b2, E);

    int node_grid = (N + TILE_N - 1) / TILE_N;
    node_kernel<<<node_grid, 256, NODE_SMEM>>>(W3, b3, W4, b4, (float*)d_out, N);
}

// round 11
// speedup vs baseline: 1.1772x; 1.1480x over previous
#include <cuda_runtime.h>
#include <cuda_bf16.h>
#include <cstdint>
#include <math.h>

// ---------------------------------------------------------------------------
// SchnetConv — R8 structure (mma.sync m16n8k16 bf16 hi/lo 3-term split,
// 16 rows/warp, scalar red.global.v2 epilogue) + persistent edge CTAs:
// weights staged ONCE per CTA, then a sync-free warp-local tile loop.
// ---------------------------------------------------------------------------

#define Dc       64
#define Rc       128
#define TILE_E   128
#define TILE_N   64
#define WST      68
#define N_MAX    100000
#define EDGE_GRID 296      // 2 CTAs/SM x 148 SMs

__device__ float g_s[(size_t)N_MAX * Dc];
__device__ float g_cnt[N_MAX];
// fragment-ordered weight image: B1 [8ks][8nt][32lane] uint4{hix,hiy,lox,loy} =32KB,
// then B2 [4ks][8nt][32lane] uint4 = 16KB
__device__ __align__(16) unsigned char g_Bimg[49152];

// SMEM layout (bytes)
#define OFF_B1    0
#define OFF_B2    32768
#define OFF_A2HI  49152     // 8 warps x 2048B (16 rows x 128B, swizzled)
#define OFF_A2LO  65536
#define OFF_BIAS  81920     // b1[64], b2[64]
#define SMEM_EDGE 82432

// ---- helpers ---------------------------------------------------------------
__device__ __forceinline__ float ssp_f(float x) {
    float e = __expf(-fabsf(x));
    return fmaxf(x, 0.0f) + log1pf(e) - 0.69314718055994531f;
}
__device__ __forceinline__ uint32_t swz(uint32_t off) { return off ^ ((off >> 3) & 0x70); }
__device__ __forceinline__ int wswz(int j) { return j + (((j >> 5) & 1) << 2); }

__device__ __forceinline__ uint32_t smem_u32(const void* p) {
    uint32_t a;
    asm("{ .reg .u64 t; cvta.to.shared.u64 t, %1; cvt.u32.u64 %0, t; }" : "=r"(a) : "l"(p));
    return a;
}
// x = hi + lo (bf16 each); packs (x0 -> low half, x1 -> high half)
__device__ __forceinline__ void split2(float x0, float x1, uint32_t& hi, uint32_t& lo) {
    asm("cvt.rn.bf16x2.f32 %0, %1, %2;" : "=r"(hi) : "f"(x1), "f"(x0));
    float h0 = __uint_as_float(hi << 16);
    float h1 = __uint_as_float(hi & 0xffff0000u);
    asm("cvt.rn.bf16x2.f32 %0, %1, %2;" : "=r"(lo) : "f"(x1 - h1), "f"(x0 - h0));
}
__device__ __forceinline__ void mma16816(float* c, const uint32_t* a, uint32_t b0, uint32_t b1) {
    asm volatile(
        "mma.sync.aligned.m16n8k16.row.col.f32.bf16.bf16.f32 "
        "{%0,%1,%2,%3}, {%4,%5,%6,%7}, {%8,%9}, {%0,%1,%2,%3};"
        : "+f"(c[0]), "+f"(c[1]), "+f"(c[2]), "+f"(c[3])
        : "r"(a[0]), "r"(a[1]), "r"(a[2]), "r"(a[3]), "r"(b0), "r"(b1));
}
__device__ __forceinline__ void ldmx4(uint32_t* r, uint32_t addr) {
    asm volatile("ldmatrix.sync.aligned.m8n8.x4.shared.b16 {%0,%1,%2,%3}, [%4];"
        : "=r"(r[0]), "=r"(r[1]), "=r"(r[2]), "=r"(r[3]) : "r"(addr));
}

// ---------------------------------------------------------------------------
__global__ void zero_kernel(int n_nodes) {
    int i = blockIdx.x * 256 + threadIdx.x;
    int t4 = n_nodes * (Dc / 4);
    if (i < t4) ((float4*)g_s)[i] = make_float4(0.f, 0.f, 0.f, 0.f);
    if (i < n_nodes) g_cnt[i] = 0.0f;
}

// Build fragment-ordered hi/lo weight image. 2048 B1 entries, 1024 B2 entries.
__global__ void prep_kernel(const float* __restrict__ W1, const float* __restrict__ W2) {
    int i = blockIdx.x * 256 + threadIdx.x;
    if (i < 2048) {   // B1: idx = (ks*8+nt)*32+lane
        int lane = i & 31, nt = (i >> 5) & 7, ks = i >> 8;
        int tid4 = lane & 3, g = lane >> 2;
        int k0 = ks * 16 + tid4 * 2;
        int n  = nt * 8 + g;
        float e00 = W1[(k0    ) * Dc + n], e01 = W1[(k0 + 1) * Dc + n];
        float e10 = W1[(k0 + 8) * Dc + n], e11 = W1[(k0 + 9) * Dc + n];
        uint32_t hx, lx, hy, ly;
        split2(e00, e01, hx, lx);
        split2(e10, e11, hy, ly);
        uint4 v; v.x = hx; v.y = hy; v.z = lx; v.w = ly;
        ((uint4*)g_Bimg)[i] = v;
    }
    if (i < 1024) {   // B2
        int lane = i & 31, nt = (i >> 5) & 7, ks = i >> 8;
        int tid4 = lane & 3, g = lane >> 2;
        int k0 = ks * 16 + tid4 * 2;
        int n  = nt * 8 + g;
        float e00 = W2[(k0    ) * Dc + n], e01 = W2[(k0 + 1) * Dc + n];
        float e10 = W2[(k0 + 8) * Dc + n], e11 = W2[(k0 + 9) * Dc + n];
        uint32_t hx, lx, hy, ly;
        split2(e00, e01, hx, lx);
        split2(e10, e11, hy, ly);
        uint4 v; v.x = hx; v.y = hy; v.z = lx; v.w = ly;
        ((uint4*)(g_Bimg + OFF_B2))[i] = v;
    }
}

// ---------------------------------------------------------------------------
// Persistent edge kernel: weights staged once, then sync-free warp-local
// loop over 128-edge tiles (8 warps x 16 rows each, R8 pipeline).
// ---------------------------------------------------------------------------
__global__ __launch_bounds__(256, 2)
void edge_kernel(const float* __restrict__ bf, const float* __restrict__ eh,
                 const float* __restrict__ nh, const int* __restrict__ src,
                 const int* __restrict__ dst,
                 const float* __restrict__ b1, const float* __restrict__ b2,
                 int E, int ntiles)
{
    extern __shared__ unsigned char smx[];
    const uint32_t sb = smem_u32(smx);
    const int t = threadIdx.x, w = t >> 5, lane = t & 31;
    const int g = lane >> 2, tid4 = lane & 3;

    // one-time stage: weight fragments (48KB) + biases
    {
        const uint4* gi = (const uint4*)g_Bimg;
        uint4* s = (uint4*)smx;
        for (int i = t; i < 3072; i += 256) s[i] = gi[i];
        float* sbias = (float*)(smx + OFF_BIAS);
        if (t < Dc) sbias[t] = b1[t];
        else if (t < 2 * Dc) sbias[t] = b2[t - Dc];
    }
    __syncthreads();

    const float* sb1 = (const float*)(smx + OFF_BIAS);
    const float* sb2 = sb1 + Dc;
    const uint32_t aHbase = sb + OFF_A2HI + w * 2048;
    const uint32_t aLbase = sb + OFF_A2LO + w * 2048;

    for (int tile = blockIdx.x; tile < ntiles; tile += gridDim.x) {
        const int e0 = tile * TILE_E + w * 16;   // warp's first edge row

        // clamp row pointers (rows may exceed E on the ragged tail)
        const int er0 = min(e0 + g,     E - 1);
        const int er1 = min(e0 + g + 8, E - 1);
        const bool v0 = (e0 + g)     < E;
        const bool v1 = (e0 + g + 8) < E;
        const float* p0 = bf + (size_t)er0 * Rc;
        const float* p1 = bf + (size_t)er1 * Rc;

        float acc[8][4];
#pragma unroll
        for (int nt = 0; nt < 8; ++nt)
#pragma unroll
            for (int q = 0; q < 4; ++q) acc[nt][q] = 0.f;

        // ---- GEMM1: f1raw = bf @ W1, K=128 (8 k-steps), N=64 (8 n-tiles) ----
#pragma unroll
        for (int ks = 0; ks < 8; ++ks) {
            const int k0 = ks * 16 + tid4 * 2;
            float2 x00 = *(const float2*)(p0 + k0);
            float2 x10 = *(const float2*)(p1 + k0);
            float2 x01 = *(const float2*)(p0 + k0 + 8);
            float2 x11 = *(const float2*)(p1 + k0 + 8);
            uint32_t aH[4], aL[4];
            split2(x00.x, x00.y, aH[0], aL[0]);
            split2(x10.x, x10.y, aH[1], aL[1]);
            split2(x01.x, x01.y, aH[2], aL[2]);
            split2(x11.x, x11.y, aH[3], aL[3]);
            const uint4* Bp = (const uint4*)(smx + OFF_B1) + (ks * 8) * 32 + lane;
#pragma unroll
            for (int nt = 0; nt < 8; ++nt) {
                uint4 bb = Bp[nt * 32];
                mma16816(acc[nt], aH, bb.x, bb.y);   // Ah*Bh
                mma16816(acc[nt], aH, bb.z, bb.w);   // Ah*Bl
                mma16816(acc[nt], aL, bb.x, bb.y);   // Al*Bh
            }
        }

        // ---- bias + ssp + hi/lo split -> per-warp A2 strips (swizzled) ----
#pragma unroll
        for (int nt = 0; nt < 8; ++nt) {
            int n = nt * 8 + tid4 * 2;
            float f0 = ssp_f(acc[nt][0] + sb1[n]);
            float f1 = ssp_f(acc[nt][1] + sb1[n + 1]);
            float f2 = ssp_f(acc[nt][2] + sb1[n]);
            float f3 = ssp_f(acc[nt][3] + sb1[n + 1]);
            uint32_t h01, l01, h23, l23;
            split2(f0, f1, h01, l01);
            split2(f2, f3, h23, l23);
            uint32_t o0 = swz((uint32_t)g       * 128 + (uint32_t)n * 2);
            uint32_t o1 = swz((uint32_t)(g + 8) * 128 + (uint32_t)n * 2);
            asm volatile("st.shared.b32 [%0], %1;" :: "r"(aHbase + o0), "r"(h01) : "memory");
            asm volatile("st.shared.b32 [%0], %1;" :: "r"(aHbase + o1), "r"(h23) : "memory");
            asm volatile("st.shared.b32 [%0], %1;" :: "r"(aLbase + o0), "r"(l01) : "memory");
            asm volatile("st.shared.b32 [%0], %1;" :: "r"(aLbase + o1), "r"(l23) : "memory");
#pragma unroll
            for (int q = 0; q < 4; ++q) acc[nt][q] = 0.f;
        }
        __syncwarp();

        // ---- GEMM2: f2raw = f1 @ W2, K=64 (4 k-steps) ----
        {
            const int lrow = lane & 15, half = lane >> 4;
#pragma unroll
            for (int ks = 0; ks < 4; ++ks) {
                uint32_t off = swz((uint32_t)lrow * 128 + (uint32_t)ks * 32 + (uint32_t)half * 16);
                uint32_t aH[4], aL[4];
                ldmx4(aH, aHbase + off);
                ldmx4(aL, aLbase + off);
                const uint4* Bp = (const uint4*)(smx + OFF_B2) + (ks * 8) * 32 + lane;
#pragma unroll
                for (int nt = 0; nt < 8; ++nt) {
                    uint4 bb = Bp[nt * 32];
                    mma16816(acc[nt], aH, bb.x, bb.y);
                    mma16816(acc[nt], aH, bb.z, bb.w);
                    mma16816(acc[nt], aL, bb.x, bb.y);
                }
            }
        }
        __syncwarp();   // A2 strip reads complete before next tile overwrites

        // ---- epilogue: m = f2 * eh * nh[src]; red.global.v2 to g_s ----
        int sv0 = 0, dv0 = 0, sv1 = 0, dv1 = 0;
        if (v0) { sv0 = src[e0 + g];     dv0 = dst[e0 + g]; }
        if (v1) { sv1 = src[e0 + g + 8]; dv1 = dst[e0 + g + 8]; }
        if (tid4 == 0) {
            if (v0) atomicAdd(&g_cnt[dv0], 1.0f);
            if (v1) atomicAdd(&g_cnt[dv1], 1.0f);
        }
#pragma unroll
        for (int nt = 0; nt < 8; ++nt) {
            int n = nt * 8 + tid4 * 2;
            if (v0) {
                float f0 = ssp_f(acc[nt][0] + sb2[n]);
                float f1 = ssp_f(acc[nt][1] + sb2[n + 1]);
                float2 ev = *(const float2*)&eh[(size_t)(e0 + g) * Dc + n];
                float2 nv = *(const float2*)&nh[(size_t)sv0 * Dc + n];
                float m0 = f0 * ev.x * nv.x;
                float m1 = f1 * ev.y * nv.y;
                float* gp = &g_s[(size_t)dv0 * Dc + n];
                asm volatile("red.global.add.v2.f32 [%0], {%1, %2};"
                             :: "l"(gp), "f"(m0), "f"(m1) : "memory");
            }
            if (v1) {
                float f2 = ssp_f(acc[nt][2] + sb2[n]);
                float f3 = ssp_f(acc[nt][3] + sb2[n + 1]);
                float2 ev = *(const float2*)&eh[(size_t)(e0 + g + 8) * Dc + n];
                float2 nv = *(const float2*)&nh[(size_t)sv1 * Dc + n];
                float m2 = f2 * ev.x * nv.x;
                float m3 = f3 * ev.y * nv.y;
                float* gp = &g_s[(size_t)dv1 * Dc + n];
                asm volatile("red.global.add.v2.f32 [%0], {%1, %2};"
                             :: "l"(gp), "f"(m2), "f"(m3) : "memory");
            }
        }
    }
}

// ---------------------------------------------------------------------------
// Node kernel: mean -> MLP3 -> MLP4 (validated R5/R8)
// ---------------------------------------------------------------------------
__global__ __launch_bounds__(256)
void node_kernel(const float* __restrict__ W3, const float* __restrict__ b3,
                 const float* __restrict__ W4, const float* __restrict__ b4,
                 float* __restrict__ out, int N)
{
    extern __shared__ float sm[];
    float* W3s  = sm;
    float* W4s  = W3s + Dc * WST;
    float* b3s  = W4s + Dc * WST;
    float* b4s  = b3s + Dc;
    float* cS   = b4s + Dc;
    float* aggS = cS + TILE_N;
    float* h1S  = aggS + TILE_N * WST;

    const int t      = threadIdx.x;
    const int n_base = blockIdx.x * TILE_N;

    for (int i = t; i < Dc * Dc; i += 256) {
        int k = i >> 6, j = i & 63;
        int js = wswz(j);
        W3s[k * WST + js] = W3[i];
        W4s[k * WST + js] = W4[i];
    }
    if (t < Dc) { b3s[t] = b3[t]; b4s[t] = b4[t]; }
    if (t < TILE_N) {
        int n = n_base + t;
        float c = (n < N) ? g_cnt[n] : 0.0f;
        cS[t] = (c > 0.0f) ? (1.0f / c) : 0.0f;
    }
    __syncthreads();

    for (int i4 = t; i4 < TILE_N * (Dc / 4); i4 += 256) {
        int nl = i4 >> 4;
        int k4 = (i4 & 15) << 2;
        int n  = n_base + nl;
        float4 v = make_float4(0.f, 0.f, 0.f, 0.f);
        if (n < N) {
            v = *(const float4*)&g_s[(size_t)n * Dc + k4];
            float inv = cS[nl];
            v.x *= inv; v.y *= inv; v.z *= inv; v.w *= inv;
        }
        *(float4*)&aggS[nl * WST + k4] = v;
    }
    __syncthreads();

    const int tj = t & 7;
    const int tn = t >> 3;
    const int j0 = tj << 3;
    const int jo = wswz(j0);
    const int n0 = tn << 1;

    float acc[2][8];
#pragma unroll
    for (int a = 0; a < 2; ++a)
#pragma unroll
        for (int b = 0; b < 8; ++b) acc[a][b] = 0.f;

#pragma unroll 8
    for (int k = 0; k < Dc; ++k) {
        float4 wA = *(const float4*)&W3s[k * WST + jo];
        float4 wB = *(const float4*)&W3s[k * WST + jo + 4];
        float w[8] = {wA.x, wA.y, wA.z, wA.w, wB.x, wB.y, wB.z, wB.w};
        float x0 = aggS[(n0 + 0) * WST + k];
        float x1 = aggS[(n0 + 1) * WST + k];
#pragma unroll
        for (int b = 0; b < 8; ++b) {
            acc[0][b] = fmaf(x0, w[b], acc[0][b]);
            acc[1][b] = fmaf(x1, w[b], acc[1][b]);
        }
    }
#pragma unroll
    for (int a = 0; a < 2; ++a) {
        float h[8];
#pragma unroll
        for (int b = 0; b < 8; ++b) h[b] = ssp_f(acc[a][b] + b3s[j0 + b]);
        *(float4*)&h1S[(n0 + a) * WST + j0]     = make_float4(h[0], h[1], h[2], h[3]);
        *(float4*)&h1S[(n0 + a) * WST + j0 + 4] = make_float4(h[4], h[5], h[6], h[7]);
#pragma unroll
        for (int b = 0; b < 8; ++b) acc[a][b] = 0.f;
    }
    __syncthreads();

#pragma unroll 8
    for (int k = 0; k < Dc; ++k) {
        float4 wA = *(const float4*)&W4s[k * WST + jo];
        float4 wB = *(const float4*)&W4s[k * WST + jo + 4];
        float w[8] = {wA.x, wA.y, wA.z, wA.w, wB.x, wB.y, wB.z, wB.w};
        float x0 = h1S[(n0 + 0) * WST + k];
        float x1 = h1S[(n0 + 1) * WST + k];
#pragma unroll
        for (int b = 0; b < 8; ++b) {
            acc[0][b] = fmaf(x0, w[b], acc[0][b]);
            acc[1][b] = fmaf(x1, w[b], acc[1][b]);
        }
    }
#pragma unroll
    for (int a = 0; a < 2; ++a) {
        int n = n_base + n0 + a;
        if (n < N) {
            float o[8];
#pragma unroll
            for (int b = 0; b < 8; ++b) o[b] = ssp_f(acc[a][b] + b4s[j0 + b]);
            *(float4*)&out[(size_t)n * Dc + j0]     = make_float4(o[0], o[1], o[2], o[3]);
            *(float4*)&out[(size_t)n * Dc + j0 + 4] = make_float4(o[4], o[5], o[6], o[7]);
        }
    }
}

// ---------------------------------------------------------------------------
extern "C" void kernel_launch(void* const* d_in, const int* in_sizes, int n_in,
                              void* d_out, int out_size)
{
    const float* bf  = (const float*)d_in[0];
    const float* eh  = (const float*)d_in[1];
    const float* nh  = (const float*)d_in[2];
    const int*   src = (const int*)  d_in[3];
    const int*   dst = (const int*)  d_in[4];
    const float* W1  = (const float*)d_in[5];
    const float* b1  = (const float*)d_in[6];
    const float* W2  = (const float*)d_in[7];
    const float* b2  = (const float*)d_in[8];
    const float* W3  = (const float*)d_in[9];
    const float* b3  = (const float*)d_in[10];
    const float* W4  = (const float*)d_in[11];
    const float* b4  = (const float*)d_in[12];

    int E = in_sizes[3];
    int N = in_sizes[2] / Dc;

    const int NODE_SMEM = (2 * Dc * WST + 2 * Dc + TILE_N + 2 * TILE_N * WST) * (int)sizeof(float);

    cudaFuncSetAttribute(edge_kernel, cudaFuncAttributeMaxDynamicSharedMemorySize, SMEM_EDGE);
    cudaFuncSetAttribute(node_kernel, cudaFuncAttributeMaxDynamicSharedMemorySize, NODE_SMEM);

    int zero_grid = (N * (Dc / 4) + 255) / 256;
    zero_kernel<<<zero_grid, 256>>>(N);

    prep_kernel<<<8, 256>>>(W1, W2);

    int ntiles = (E + TILE_E - 1) / TILE_E;
    int egrid = ntiles < EDGE_GRID ? ntiles : EDGE_GRID;
    edge_kernel<<<egrid, 256, SMEM_EDGE>>>(bf, eh, nh, src, dst, b1, b2, E, ntiles);

    int node_grid = (N + TILE_N - 1) / TILE_N;
    node_kernel<<<node_grid, 256, NODE_SMEM>>>(W3, b3, W4, b4, (float*)d_out, N);
}